// round 11
// baseline (speedup 1.0000x reference)
#include <cuda_runtime.h>
#include <math.h>
#include <stdint.h>

#define HDIM 2048
#define NEXP 16
#define IDIM 768
#define TWO_I 1536
#define TMAX 2048
#define PMAX (TMAX*2)

// ---------------- device scratch ----------------
__device__ int      g_count[NEXP];
__device__ int      g_segstart[NEXP + 1];
__device__ int      g_tok_e[TMAX * 2];
__device__ float    g_tok_w[TMAX * 2];
__device__ int      g_pair_token[PMAX];
__device__ float    g_pair_w[PMAX];
__device__ unsigned g_amax_bits;                       // global weight |max| (bits)
__device__ float    g_xscale[TMAX];                    // per-token x scale
__device__ float    g_hscale[PMAX];                    // per-pair h scale
__device__ __align__(16) int8_t g_x1[(size_t)TMAX * HDIM];
__device__ __align__(16) int8_t g_x2[(size_t)TMAX * HDIM];
__device__ __align__(16) int8_t g_h1[(size_t)PMAX * IDIM];
__device__ __align__(16) int8_t g_h2[(size_t)PMAX * IDIM];
__device__ __align__(16) float  g_gu[(size_t)PMAX * TWO_I];
__device__ float    g_logits_fallback[TMAX * NEXP];

// ---------------- portable PTX helpers ----------------
__device__ __forceinline__ uint32_t smem_u32(const void* p) {
    uint32_t a;
    asm("{ .reg .u64 t; cvta.to.shared.u64 t, %1; cvt.u32.u64 %0, t; }" : "=r"(a) : "l"(p));
    return a;
}
#define LDMX4(r, addr) \
    asm volatile("ldmatrix.sync.aligned.m8n8.x4.shared.b16 {%0,%1,%2,%3}, [%4];" \
        : "=r"((r)[0]), "=r"((r)[1]), "=r"((r)[2]), "=r"((r)[3]) : "r"(addr))
#define IMMA(acc, a, b0, b1) \
    asm volatile("mma.sync.aligned.m16n8k32.row.col.s32.s8.s8.s32 " \
        "{%0,%1,%2,%3}, {%4,%5,%6,%7}, {%8,%9}, {%0,%1,%2,%3};" \
        : "+r"((acc)[0]), "+r"((acc)[1]), "+r"((acc)[2]), "+r"((acc)[3]) \
        : "r"((a)[0]), "r"((a)[1]), "r"((a)[2]), "r"((a)[3]), "r"(b0), "r"(b1))
#define STSV2(addr, x, y) \
    asm volatile("st.shared.v2.b32 [%0], {%1,%2};" :: "r"((uint32_t)(addr)), "r"(x), "r"(y) : "memory")
#define STSV4(addr, x, y, z, w) \
    asm volatile("st.shared.v4.b32 [%0], {%1,%2,%3,%4};" :: "r"((uint32_t)(addr)), \
        "r"(x), "r"(y), "r"(z), "r"(w) : "memory")

// XOR swizzle on 64B rows: [digit1 32B | digit2 32B]; digit2 addr = digit1 ^ 32.
__device__ __forceinline__ uint32_t swz(uint32_t row, uint32_t colbyte) {
    return (row * 64 + colbyte) ^ ((row & 6) << 3);
}

// fixed-point split: v -> d1*128 + d2 at scale inv (v*inv in [-16256,16256])
__device__ __forceinline__ void q8(float v, float inv, int& a, int& b) {
    float r = rintf(v * inv);
    r = fminf(fmaxf(r, -16256.f), 16256.f);
    float d1 = rintf(r * (1.f / 128.f));
    a = (int)d1;
    b = (int)(r - 128.f * d1);
}
__device__ __forceinline__ uint32_t pack4(int a0, int a1, int a2, int a3) {
    return (uint32_t)(a0 & 255) | ((uint32_t)(a1 & 255) << 8) |
           ((uint32_t)(a2 & 255) << 16) | ((uint32_t)a3 << 24);
}

// ---------------- weight amax ----------------
__global__ __launch_bounds__(256) void amax_kernel(
    const float4* __restrict__ a, int n4a, const float4* __restrict__ b, int n4b)
{
    float m = 0.f;
    int stride = gridDim.x * blockDim.x;
    for (int i = blockIdx.x * blockDim.x + threadIdx.x; i < n4a; i += stride) {
        float4 v = a[i];
        m = fmaxf(m, fmaxf(fmaxf(fabsf(v.x), fabsf(v.y)), fmaxf(fabsf(v.z), fabsf(v.w))));
    }
    for (int i = blockIdx.x * blockDim.x + threadIdx.x; i < n4b; i += stride) {
        float4 v = b[i];
        m = fmaxf(m, fmaxf(fmaxf(fabsf(v.x), fabsf(v.y)), fmaxf(fabsf(v.z), fabsf(v.w))));
    }
#pragma unroll
    for (int off = 16; off > 0; off >>= 1) m = fmaxf(m, __shfl_down_sync(0xffffffffu, m, off));
    __shared__ float sm[8];
    int warp = threadIdx.x >> 5, lane = threadIdx.x & 31;
    if (lane == 0) sm[warp] = m;
    __syncthreads();
    if (threadIdx.x == 0) {
        float bm = sm[0];
#pragma unroll
        for (int w = 1; w < 8; w++) bm = fmaxf(bm, sm[w]);
        atomicMax(&g_amax_bits, __float_as_uint(bm));
    }
}

// ---------------- router + x quantize ----------------
__global__ __launch_bounds__(128) void router_kernel(
    const float* __restrict__ x, const float* __restrict__ gw, float* __restrict__ logits, int T)
{
    int t = blockIdx.x, tid = threadIdx.x;
    float acc[NEXP];
#pragma unroll
    for (int e = 0; e < NEXP; e++) acc[e] = 0.f;
    float am = 0.f;
    const float* xr = x + (size_t)t * HDIM;
    for (int h = tid; h < HDIM; h += 128) {
        float xv = xr[h];
        am = fmaxf(am, fabsf(xv));
#pragma unroll
        for (int e = 0; e < NEXP; e++) acc[e] += xv * gw[e * HDIM + h];
    }
#pragma unroll
    for (int e = 0; e < NEXP; e++)
#pragma unroll
        for (int off = 16; off > 0; off >>= 1) acc[e] += __shfl_down_sync(0xffffffffu, acc[e], off);
#pragma unroll
    for (int off = 16; off > 0; off >>= 1) am = fmaxf(am, __shfl_down_sync(0xffffffffu, am, off));

    __shared__ float sred[4][NEXP];
    __shared__ float slog[NEXP];
    __shared__ float samax[4];
    int warp = tid >> 5, lane = tid & 31;
    if (lane == 0) {
#pragma unroll
        for (int e = 0; e < NEXP; e++) sred[warp][e] = acc[e];
        samax[warp] = am;
    }
    __syncthreads();
    if (tid < NEXP) {
        float v = sred[0][tid] + sred[1][tid] + sred[2][tid] + sred[3][tid];
        slog[tid] = v;
        logits[t * NEXP + tid] = v;
    }
    __syncthreads();
    float amax = fmaxf(fmaxf(samax[0], samax[1]), fmaxf(samax[2], samax[3]));
    float inv = amax > 0.f ? 16256.f / amax : 0.f;
    if (tid == 0) g_xscale[t] = amax * (1.f / 16256.f);

    // quantize x row -> d1/d2 planes
    for (int h = tid; h < HDIM; h += 128) {
        int d1, d2;
        q8(xr[h], inv, d1, d2);
        g_x1[(size_t)t * HDIM + h] = (int8_t)d1;
        g_x2[(size_t)t * HDIM + h] = (int8_t)d2;
    }

    if (tid == 0) {
        int i0 = 0; float v0 = slog[0];
#pragma unroll
        for (int e = 1; e < NEXP; e++) if (slog[e] > v0) { v0 = slog[e]; i0 = e; }
        int i1 = -1; float v1 = -INFINITY;
#pragma unroll
        for (int e = 0; e < NEXP; e++) { if (e == i0) continue; if (slog[e] > v1) { v1 = slog[e]; i1 = e; } }
        float e1 = expf(v1 - v0);
        float w0 = 1.f / (1.f + e1);
        g_tok_e[t * 2 + 0] = i0; g_tok_w[t * 2 + 0] = w0;
        g_tok_e[t * 2 + 1] = i1; g_tok_w[t * 2 + 1] = e1 * w0;
        atomicAdd(&g_count[i0], 1);
        atomicAdd(&g_count[i1], 1);
    }
}

// ---------------- offsets + dispatch ----------------
__global__ __launch_bounds__(1024) void dispatch_kernel(int T)
{
    __shared__ int cur[NEXP];
    int tid = threadIdx.x;
    if (tid == 0) {
        int off = 0;
#pragma unroll
        for (int e = 0; e < NEXP; e++) { g_segstart[e] = off; cur[e] = off; off += g_count[e]; }
        g_segstart[NEXP] = off;
    }
    __syncthreads();
    for (int t = tid; t < T; t += 1024) {
#pragma unroll
        for (int s = 0; s < 2; s++) {
            int e = g_tok_e[t * 2 + s];
            int pos = atomicAdd(&cur[e], 1);
            g_pair_token[pos] = t;
            g_pair_w[pos]     = g_tok_w[t * 2 + s];
        }
    }
}

// =============== int8x2 grouped GEMM ===============
// CTA 128x64, 256 threads, 8 warps (4m x 2n), warp tile 32x32, BK=32.
// Stage: A 128 rows x 64B = 8KB at +0; B 64 rows x 64B = 4KB at +8192. 2 stages = 24KB.
#define STAGE 12288
#define GSMEM 24576

// MODE 0: gu (A = x planes gathered by pair_token; C = g_gu fp32)
// MODE 1: down (A = h planes, row = pair index; atomic scatter into out)
template<int KDIM, int MODE>
__global__ __launch_bounds__(256, 1) void gemm_i8(
    const int8_t* __restrict__ Ad1, const int8_t* __restrict__ Ad2,
    const float* __restrict__ Ascale, const float* __restrict__ B,
    float* __restrict__ C, size_t b_expert_stride)
{
    int e = blockIdx.z;
    int seg0 = g_segstart[e];
    int cnt  = g_segstart[e + 1] - seg0;
    int m0 = blockIdx.x * 128;
    if (m0 >= cnt) return;
    int n0 = blockIdx.y * 64;

    extern __shared__ char smem[];
    uint32_t sbase = smem_u32(smem);

    int tid = threadIdx.x;
    int lane = tid & 31, wid = tid >> 5;
    int warp_m = wid >> 1;     // 0..3
    int warp_n = wid & 1;      // 0..1

    float wamax = __uint_as_float(g_amax_bits);
    float inv_b = wamax > 0.f ? 16256.f / wamax : 0.f;
    float sb_scale = wamax * (1.f / 16256.f);

    // -------- A loader: 2 threads/row, 16B halves --------
    int arow_l = tid >> 1, ahalf = tid & 1;
    int mrow = m0 + arow_l; if (mrow >= cnt) mrow = cnt - 1;
    int arow = (MODE == 0) ? g_pair_token[seg0 + mrow] : (seg0 + mrow);
    const int8_t* a1p = Ad1 + (size_t)arow * KDIM + ahalf * 16;
    const int8_t* a2p = Ad2 + (size_t)arow * KDIM + ahalf * 16;
    uint32_t stsA = swz((uint32_t)arow_l, (uint32_t)(ahalf * 16));

    // -------- B loader: 4 threads/row, 8 fp32 each --------
    int rowb = tid >> 2, q = tid & 3;
    const float* bptr = B + (size_t)e * b_expert_stride + (size_t)(n0 + rowb) * KDIM + q * 8;
    uint32_t stsB = 8192 + swz((uint32_t)rowb, (uint32_t)(q * 8));

    // -------- ldmatrix offsets --------
    int a_r = lane & 15, a_k = lane >> 4;
    int b_n = (lane & 7) + ((lane & 16) ? 8 : 0);
    int b_k = (lane & 8) ? 1 : 0;
    uint32_t a_off[2], b_off[2];
#pragma unroll
    for (int mf = 0; mf < 2; mf++)
        a_off[mf] = swz((uint32_t)(warp_m * 32 + mf * 16 + a_r), (uint32_t)(a_k * 16));
#pragma unroll
    for (int nf = 0; nf < 2; nf++)
        b_off[nf] = 8192 + swz((uint32_t)(warp_n * 32 + nf * 16 + b_n), (uint32_t)(b_k * 16));

    int acc1[2][4][4], acc2[2][4][4];
#pragma unroll
    for (int mf = 0; mf < 2; mf++)
#pragma unroll
        for (int j = 0; j < 4; j++)
#pragma unroll
            for (int p = 0; p < 4; p++) { acc1[mf][j][p] = 0; acc2[mf][j][p] = 0; }

    const int NCH = KDIM / 32;
    uint4 pa1, pa2;
    float4 pb0, pb1;

    auto ldg_chunk = [&](int c) {
        pa1 = *(const uint4*)(a1p + c * 32);
        pa2 = *(const uint4*)(a2p + c * 32);
        pb0 = *(const float4*)(bptr + c * 32);
        pb1 = *(const float4*)(bptr + c * 32 + 4);
    };
    auto sts_chunk = [&](uint32_t sb) {
        STSV4(sb + stsA,         pa1.x, pa1.y, pa1.z, pa1.w);
        STSV4(sb + (stsA ^ 32u), pa2.x, pa2.y, pa2.z, pa2.w);
        int d1[8], d2[8];
        q8(pb0.x, inv_b, d1[0], d2[0]); q8(pb0.y, inv_b, d1[1], d2[1]);
        q8(pb0.z, inv_b, d1[2], d2[2]); q8(pb0.w, inv_b, d1[3], d2[3]);
        q8(pb1.x, inv_b, d1[4], d2[4]); q8(pb1.y, inv_b, d1[5], d2[5]);
        q8(pb1.z, inv_b, d1[6], d2[6]); q8(pb1.w, inv_b, d1[7], d2[7]);
        STSV2(sb + stsB,         pack4(d1[0], d1[1], d1[2], d1[3]), pack4(d1[4], d1[5], d1[6], d1[7]));
        STSV2(sb + (stsB ^ 32u), pack4(d2[0], d2[1], d2[2], d2[3]), pack4(d2[4], d2[5], d2[6], d2[7]));
    };

    ldg_chunk(0);
    sts_chunk(sbase);
    ldg_chunk(1);
    __syncthreads();

#pragma unroll 2
    for (int ch = 0; ch < NCH; ch++) {
        uint32_t sb  = sbase + (ch & 1) * STAGE;
        uint32_t sbn = sbase + ((ch + 1) & 1) * STAGE;
        if (ch + 1 < NCH) sts_chunk(sbn);
        uint32_t a1f[2][4], a2f[2][4];
#pragma unroll
        for (int mf = 0; mf < 2; mf++) {
            LDMX4(a1f[mf], sb + a_off[mf]);
            LDMX4(a2f[mf], sb + (a_off[mf] ^ 32u));
        }
#pragma unroll
        for (int nf = 0; nf < 2; nf++) {
            uint32_t b1f[4], b2f[4];
            LDMX4(b1f, sb + b_off[nf]);
            LDMX4(b2f, sb + (b_off[nf] ^ 32u));
#pragma unroll
            for (int mf = 0; mf < 2; mf++)
#pragma unroll
                for (int jj = 0; jj < 2; jj++) {
                    int j = nf * 2 + jj;
                    IMMA(acc1[mf][j], a1f[mf], b1f[jj * 2], b1f[jj * 2 + 1]);
                    IMMA(acc2[mf][j], a1f[mf], b2f[jj * 2], b2f[jj * 2 + 1]);
                    IMMA(acc2[mf][j], a2f[mf], b1f[jj * 2], b1f[jj * 2 + 1]);
                }
        }
        if (ch + 2 < NCH) ldg_chunk(ch + 2);
        __syncthreads();
    }

    // -------- epilogue: out = sa*sb*(16384*acc1 + 128*acc2) --------
    int erow = lane >> 2;
    int ecol = (lane & 3) * 2;
#pragma unroll
    for (int mf = 0; mf < 2; mf++) {
        int mloc[2] = { m0 + warp_m * 32 + mf * 16 + erow, m0 + warp_m * 32 + mf * 16 + erow + 8 };
#pragma unroll
        for (int rr = 0; rr < 2; rr++) {
            if (mloc[rr] >= cnt) continue;
            int prow = seg0 + mloc[rr];
            float sa, w = 0.f; int tok = 0;
            if (MODE == 0) {
                tok = g_pair_token[prow];
                sa = g_xscale[tok] * sb_scale;
            } else {
                tok = g_pair_token[prow];
                w   = g_pair_w[prow];
                sa  = g_hscale[prow] * sb_scale;
            }
#pragma unroll
            for (int j = 0; j < 4; j++) {
                int nglob = n0 + warp_n * 32 + j * 8 + ecol;
                float f0 = 16384.f * (float)acc1[mf][j][rr * 2 + 0] + 128.f * (float)acc2[mf][j][rr * 2 + 0];
                float f1 = 16384.f * (float)acc1[mf][j][rr * 2 + 1] + 128.f * (float)acc2[mf][j][rr * 2 + 1];
                if (MODE == 0) {
                    *(float2*)(C + (size_t)prow * TWO_I + nglob) = make_float2(sa * f0, sa * f1);
                } else {
                    atomicAdd(C + (size_t)tok * HDIM + nglob,     w * sa * f0);
                    atomicAdd(C + (size_t)tok * HDIM + nglob + 1, w * sa * f1);
                }
            }
        }
    }
}

// ---------------- SwiGLU + h quantize (one block per pair row) ----------------
__global__ __launch_bounds__(256) void swiglu_hq(int npairs)
{
    int p = blockIdx.x;
    int tid = threadIdx.x;
    const float* gr = g_gu + (size_t)p * TWO_I;
    float h[3];
    float am = 0.f;
#pragma unroll
    for (int i = 0; i < 3; i++) {
        int c = tid + i * 256;
        float g = gr[c], u = gr[IDIM + c];
        h[i] = u * g / (1.f + expf(-g));
        am = fmaxf(am, fabsf(h[i]));
    }
#pragma unroll
    for (int off = 16; off > 0; off >>= 1) am = fmaxf(am, __shfl_down_sync(0xffffffffu, am, off));
    __shared__ float sm[8];
    int warp = tid >> 5, lane = tid & 31;
    if (lane == 0) sm[warp] = am;
    __syncthreads();
    float amax = sm[0];
#pragma unroll
    for (int w = 1; w < 8; w++) amax = fmaxf(amax, sm[w]);
    float inv = amax > 0.f ? 16256.f / amax : 0.f;
    if (tid == 0) g_hscale[p] = amax * (1.f / 16256.f);
#pragma unroll
    for (int i = 0; i < 3; i++) {
        int c = tid + i * 256;
        int d1, d2;
        q8(h[i], inv, d1, d2);
        g_h1[(size_t)p * IDIM + c] = (int8_t)d1;
        g_h2[(size_t)p * IDIM + c] = (int8_t)d2;
    }
}

// ---------------- launch ----------------
extern "C" void kernel_launch(void* const* d_in, const int* in_sizes, int n_in,
                              void* d_out, int out_size)
{
    const float* x   = (const float*)d_in[0];
    const float* gw  = (const float*)d_in[1];
    const float* gup = (const float*)d_in[2];
    const float* dw  = (const float*)d_in[3];
    float* out = (float*)d_out;

    int T = in_sizes[0] / HDIM;
    size_t main_sz = (size_t)T * HDIM;

    float* logits;
    if ((size_t)out_size >= main_sz + (size_t)T * NEXP) logits = out + main_sz;
    else cudaGetSymbolAddress((void**)&logits, g_logits_fallback);

    cudaFuncSetAttribute((const void*)gemm_i8<HDIM, 0>,
                         cudaFuncAttributeMaxDynamicSharedMemorySize, GSMEM);
    cudaFuncSetAttribute((const void*)gemm_i8<IDIM, 1>,
                         cudaFuncAttributeMaxDynamicSharedMemorySize, GSMEM);

    int* d_count;  cudaGetSymbolAddress((void**)&d_count, g_count);
    unsigned* d_am; cudaGetSymbolAddress((void**)&d_am, g_amax_bits);
    cudaMemsetAsync(d_count, 0, NEXP * sizeof(int), 0);
    cudaMemsetAsync(d_am, 0, sizeof(unsigned), 0);
    cudaMemsetAsync(out, 0, main_sz * sizeof(float), 0);

    amax_kernel<<<1024, 256>>>((const float4*)gup, in_sizes[2] / 4,
                               (const float4*)dw,  in_sizes[3] / 4);
    router_kernel<<<T, 128>>>(x, gw, logits, T);
    dispatch_kernel<<<1, 1024>>>(T);

    int mtiles = (T + 127) / 128;
    float* d_gu; cudaGetSymbolAddress((void**)&d_gu, g_gu);
    int8_t *d_x1, *d_x2, *d_h1, *d_h2;
    float *d_xs, *d_hs;
    cudaGetSymbolAddress((void**)&d_x1, g_x1);
    cudaGetSymbolAddress((void**)&d_x2, g_x2);
    cudaGetSymbolAddress((void**)&d_h1, g_h1);
    cudaGetSymbolAddress((void**)&d_h2, g_h2);
    cudaGetSymbolAddress((void**)&d_xs, g_xscale);
    cudaGetSymbolAddress((void**)&d_hs, g_hscale);

    dim3 gu_grid(mtiles, TWO_I / 64, NEXP);
    gemm_i8<HDIM, 0><<<gu_grid, 256, GSMEM>>>(d_x1, d_x2, d_xs, gup, d_gu, (size_t)TWO_I * HDIM);

    swiglu_hq<<<2 * T, 256>>>(2 * T);

    dim3 dn_grid(mtiles, HDIM / 64, NEXP);
    gemm_i8<IDIM, 1><<<dn_grid, 256, GSMEM>>>(d_h1, d_h2, d_hs, dw, out, (size_t)HDIM * IDIM);
}

// round 12
// speedup vs baseline: 2.9559x; 2.9559x over previous
#include <cuda_runtime.h>
#include <cuda_fp16.h>
#include <math.h>
#include <stdint.h>

#define HDIM 2048
#define NEXP 16
#define IDIM 768
#define TWO_I 1536
#define TMAX 2048
#define PMAX (TMAX*2)

typedef unsigned short ushort_t;

// ---------------- device scratch ----------------
__device__ int   g_count[NEXP];
__device__ int   g_segstart[NEXP + 1];
__device__ int   g_tok_e[TMAX * 2];
__device__ float g_tok_w[TMAX * 2];
__device__ int   g_pair_token[PMAX];
__device__ float g_pair_w[PMAX];
__device__ __align__(16) float    g_gu[(size_t)PMAX * TWO_I];
__device__ __align__(16) ushort_t g_h_hi[(size_t)PMAX * IDIM];   // h digit1 (f16)
__device__ __align__(16) ushort_t g_h_lo[(size_t)PMAX * IDIM];   // h digit2 (f16)
__device__ float g_logits_fallback[TMAX * NEXP];

// ---------------- portable PTX helpers ----------------
__device__ __forceinline__ uint32_t smem_u32(const void* p) {
    uint32_t a;
    asm("{ .reg .u64 t; cvta.to.shared.u64 t, %1; cvt.u32.u64 %0, t; }" : "=r"(a) : "l"(p));
    return a;
}
#define LDMX4(r, addr) \
    asm volatile("ldmatrix.sync.aligned.m8n8.x4.shared.b16 {%0,%1,%2,%3}, [%4];" \
        : "=r"((r)[0]), "=r"((r)[1]), "=r"((r)[2]), "=r"((r)[3]) : "r"(addr))
#define MMA(acc, a, b0, b1) \
    asm volatile("mma.sync.aligned.m16n8k16.row.col.f32.f16.f16.f32 " \
        "{%0,%1,%2,%3}, {%4,%5,%6,%7}, {%8,%9}, {%0,%1,%2,%3};" \
        : "+f"((acc)[0]), "+f"((acc)[1]), "+f"((acc)[2]), "+f"((acc)[3]) \
        : "r"((a)[0]), "r"((a)[1]), "r"((a)[2]), "r"((a)[3]), "r"(b0), "r"(b1))
#define STSV2(addr, x, y) \
    asm volatile("st.shared.v2.b32 [%0], {%1,%2};" :: "r"((uint32_t)(addr)), "r"(x), "r"(y) : "memory")
#define STSV4(addr, x, y, z, w) \
    asm volatile("st.shared.v4.b32 [%0], {%1,%2,%3,%4};" :: "r"((uint32_t)(addr)), \
        "r"(x), "r"(y), "r"(z), "r"(w) : "memory")

// XOR swizzle for 64B-pitch rows (16B-granular; never add offsets after swizzling)
__device__ __forceinline__ uint32_t swz(uint32_t row, uint32_t colbyte) {
    return (row * 64 + colbyte) ^ ((row & 6) << 3);
}

// f16 pack: {x,y} -> f16x2 (x low)
__device__ __forceinline__ uint32_t packh2(float x, float y) {
    uint32_t r;
    asm("cvt.rn.f16x2.f32 %0, %1, %2;" : "=r"(r) : "f"(y), "f"(x));
    return r;
}
// f16 two-digit split: {x,y} -> hi f16x2, lo f16x2 (lo = rn(v - hi))
__device__ __forceinline__ void split2h(float x, float y, uint32_t& hi, uint32_t& lo) {
    uint32_t h = packh2(x, y);
    float hx, hy;
    asm("{ .reg .f16 a,b; mov.b32 {a,b}, %2; cvt.f32.f16 %0, a; cvt.f32.f16 %1, b; }"
        : "=f"(hx), "=f"(hy) : "r"(h));
    lo = packh2(x - hx, y - hy);
    hi = h;
}
__device__ __forceinline__ void split4h(float4 v, uint32_t& h01, uint32_t& h23,
                                        uint32_t& l01, uint32_t& l23) {
    split2h(v.x, v.y, h01, l01);
    split2h(v.z, v.w, h23, l23);
}

// ---------------- small kernels ----------------
__global__ __launch_bounds__(128) void router_kernel(
    const float* __restrict__ x, const float* __restrict__ gw, float* __restrict__ logits, int T)
{
    int t = blockIdx.x, tid = threadIdx.x;
    float acc[NEXP];
#pragma unroll
    for (int e = 0; e < NEXP; e++) acc[e] = 0.f;
    const float* xr = x + (size_t)t * HDIM;
    for (int h = tid; h < HDIM; h += 128) {
        float xv = xr[h];
#pragma unroll
        for (int e = 0; e < NEXP; e++) acc[e] += xv * gw[e * HDIM + h];
    }
#pragma unroll
    for (int e = 0; e < NEXP; e++)
#pragma unroll
        for (int off = 16; off > 0; off >>= 1) acc[e] += __shfl_down_sync(0xffffffffu, acc[e], off);
    __shared__ float sred[4][NEXP];
    __shared__ float slog[NEXP];
    int warp = tid >> 5, lane = tid & 31;
    if (lane == 0)
#pragma unroll
        for (int e = 0; e < NEXP; e++) sred[warp][e] = acc[e];
    __syncthreads();
    if (tid < NEXP) {
        float v = sred[0][tid] + sred[1][tid] + sred[2][tid] + sred[3][tid];
        slog[tid] = v;
        logits[t * NEXP + tid] = v;
    }
    __syncthreads();
    if (tid == 0) {
        int i0 = 0; float v0 = slog[0];
#pragma unroll
        for (int e = 1; e < NEXP; e++) if (slog[e] > v0) { v0 = slog[e]; i0 = e; }
        int i1 = -1; float v1 = -INFINITY;
#pragma unroll
        for (int e = 0; e < NEXP; e++) { if (e == i0) continue; if (slog[e] > v1) { v1 = slog[e]; i1 = e; } }
        float e1 = expf(v1 - v0);
        float inv = 1.f / (1.f + e1);
        g_tok_e[t * 2 + 0] = i0; g_tok_w[t * 2 + 0] = inv;
        g_tok_e[t * 2 + 1] = i1; g_tok_w[t * 2 + 1] = e1 * inv;
        atomicAdd(&g_count[i0], 1);
        atomicAdd(&g_count[i1], 1);
    }
}

// offsets + dispatch merged, single block
__global__ __launch_bounds__(1024) void dispatch_kernel(int T)
{
    __shared__ int cur[NEXP];
    int tid = threadIdx.x;
    if (tid == 0) {
        int off = 0;
#pragma unroll
        for (int e = 0; e < NEXP; e++) { g_segstart[e] = off; cur[e] = off; off += g_count[e]; }
        g_segstart[NEXP] = off;
    }
    __syncthreads();
    for (int t = tid; t < T; t += 1024) {
#pragma unroll
        for (int s = 0; s < 2; s++) {
            int e = g_tok_e[t * 2 + s];
            int pos = atomicAdd(&cur[e], 1);
            g_pair_token[pos] = t;
            g_pair_w[pos]     = g_tok_w[t * 2 + s];
        }
    }
}

// ---------------- grouped GEMM: f16 two-digit A x single-f16 B ----------------
// CTA 128x128, 256 threads, 8 warps (2m x 4n), warp tile 64x32, BK=32.
// Stage: A_hi 0 (8K) | A_lo 8K (8K) | B 16K (8K) = 24KB; 2 stages = 48KB.
#define STAGE 24576
#define GSMEM 49152

// AKIND 0: A fp32 gathered (gu), C = g_gu;  AKIND 1: A pre-split f16 (down), atomic scatter into out
template<int KDIM, int AKIND>
__global__ __launch_bounds__(256, 1) void gemm2(
    const float* __restrict__ Af32, const float* __restrict__ B,
    float* __restrict__ C, int ldc, size_t b_expert_stride)
{
    int e = blockIdx.z;
    int seg0 = g_segstart[e];
    int cnt  = g_segstart[e + 1] - seg0;
    int m0 = blockIdx.x * 128;
    if (m0 >= cnt) return;
    int n0 = blockIdx.y * 128;

    extern __shared__ char smem[];
    uint32_t sbase = smem_u32(smem);

    int tid = threadIdx.x;
    int lane = tid & 31, wid = tid >> 5;
    int warp_m = wid >> 2;
    int warp_n = wid & 3;

    // -------- loader setup --------
    int row  = tid >> 1;          // 0..127
    int half = tid & 1;
    int mrow = m0 + row; if (mrow >= cnt) mrow = cnt - 1;

    const float* aptr = nullptr;
    const uint4 *ahip = nullptr, *alop = nullptr;
    if (AKIND == 0) {
        aptr = Af32 + (size_t)g_pair_token[seg0 + mrow] * KDIM + half * 16;
    } else {
        ahip = (const uint4*)(g_h_hi + (size_t)(seg0 + mrow) * IDIM) + half * 2;
        alop = (const uint4*)(g_h_lo + (size_t)(seg0 + mrow) * IDIM) + half * 2;
    }
    const float* bptr = B + (size_t)e * b_expert_stride + (size_t)(n0 + row) * KDIM + half * 16;

    uint32_t sts8[4], sts16[2];
#pragma unroll
    for (int j = 0; j < 4; j++) sts8[j] = swz((uint32_t)row, (uint32_t)(half * 32 + j * 8));
#pragma unroll
    for (int j = 0; j < 2; j++) sts16[j] = swz((uint32_t)row, (uint32_t)(half * 32 + j * 16));

    // -------- ldmatrix offsets --------
    int a_r = lane & 15, a_k = lane >> 4;
    int b_n = (lane & 7) + ((lane & 16) ? 8 : 0);
    int b_k = (lane & 8) ? 1 : 0;
    uint32_t a_off[4][2], b_off[2][2];
#pragma unroll
    for (int mf = 0; mf < 4; mf++)
#pragma unroll
        for (int kk = 0; kk < 2; kk++)
            a_off[mf][kk] = swz((uint32_t)(warp_m * 64 + mf * 16 + a_r), (uint32_t)((kk * 2 + a_k) * 16));
#pragma unroll
    for (int nf = 0; nf < 2; nf++)
#pragma unroll
        for (int kk = 0; kk < 2; kk++)
            b_off[nf][kk] = 16384 + swz((uint32_t)(warp_n * 32 + nf * 16 + b_n), (uint32_t)((kk * 2 + b_k) * 16));

    float acc[4][4][4];
#pragma unroll
    for (int mf = 0; mf < 4; mf++)
#pragma unroll
        for (int j = 0; j < 4; j++)
#pragma unroll
            for (int q = 0; q < 4; q++) acc[mf][j][q] = 0.f;

    const int NCH = KDIM / 32;
    float4 pa[4], pb[4];
    uint4  pah[2], pal[2];

    auto ldg_chunk = [&](int c) {
        const float* bp = bptr + c * 32;
#pragma unroll
        for (int j = 0; j < 4; j++) pb[j] = ((const float4*)bp)[j];
        if (AKIND == 0) {
            const float* ap = aptr + c * 32;
#pragma unroll
            for (int j = 0; j < 4; j++) pa[j] = ((const float4*)ap)[j];
        } else {
#pragma unroll
            for (int j = 0; j < 2; j++) { pah[j] = ahip[c * 4 + j]; pal[j] = alop[c * 4 + j]; }
        }
    };
    auto sts_chunk = [&](uint32_t sb) {
        if (AKIND == 0) {
#pragma unroll
            for (int j = 0; j < 4; j++) {
                uint32_t h01, h23, l01, l23;
                split4h(pa[j], h01, h23, l01, l23);
                STSV2(sb + sts8[j],        h01, h23);
                STSV2(sb + 8192 + sts8[j], l01, l23);
            }
        } else {
#pragma unroll
            for (int j = 0; j < 2; j++) {
                STSV4(sb + sts16[j],        pah[j].x, pah[j].y, pah[j].z, pah[j].w);
                STSV4(sb + 8192 + sts16[j], pal[j].x, pal[j].y, pal[j].z, pal[j].w);
            }
        }
#pragma unroll
        for (int j = 0; j < 4; j++) {
            uint32_t b01 = packh2(pb[j].x, pb[j].y);
            uint32_t b23 = packh2(pb[j].z, pb[j].w);
            STSV2(sb + 16384 + sts8[j], b01, b23);
        }
    };

    ldg_chunk(0);
    sts_chunk(sbase);
    ldg_chunk(1);
    __syncthreads();

#pragma unroll 2
    for (int ch = 0; ch < NCH; ch++) {
        uint32_t sb  = sbase + (ch & 1) * STAGE;
        uint32_t sbn = sbase + ((ch + 1) & 1) * STAGE;
        if (ch + 1 < NCH) sts_chunk(sbn);
#pragma unroll
        for (int kk = 0; kk < 2; kk++) {
            uint32_t ahf[4][4], alf[4][4], bf[2][4];
#pragma unroll
            for (int mf = 0; mf < 4; mf++) {
                LDMX4(ahf[mf], sb + a_off[mf][kk]);
                LDMX4(alf[mf], sb + 8192 + a_off[mf][kk]);
            }
#pragma unroll
            for (int nf = 0; nf < 2; nf++) {
                LDMX4(bf[nf], sb + b_off[nf][kk]);
            }
#pragma unroll
            for (int mf = 0; mf < 4; mf++)
#pragma unroll
                for (int j = 0; j < 4; j++) {
                    uint32_t b0 = bf[j >> 1][(j & 1) * 2], b1 = bf[j >> 1][(j & 1) * 2 + 1];
                    MMA(acc[mf][j], ahf[mf], b0, b1);
                    MMA(acc[mf][j], alf[mf], b0, b1);
                }
        }
        if (ch + 2 < NCH) ldg_chunk(ch + 2);
        __syncthreads();
    }

    // -------- epilogue --------
    int erow = lane >> 2;
    int ecol = (lane & 3) * 2;
    if (AKIND == 0) {
#pragma unroll
        for (int mf = 0; mf < 4; mf++) {
            int mloc0 = m0 + warp_m * 64 + mf * 16 + erow;
            int mloc1 = mloc0 + 8;
#pragma unroll
            for (int j = 0; j < 4; j++) {
                int nglob = n0 + warp_n * 32 + j * 8 + ecol;
                if (mloc0 < cnt)
                    *(float2*)(C + (size_t)(seg0 + mloc0) * ldc + nglob) = make_float2(acc[mf][j][0], acc[mf][j][1]);
                if (mloc1 < cnt)
                    *(float2*)(C + (size_t)(seg0 + mloc1) * ldc + nglob) = make_float2(acc[mf][j][2], acc[mf][j][3]);
            }
        }
    } else {
        // weighted atomic scatter into out[t, n] (exactly 2 adds/elem)
#pragma unroll
        for (int mf = 0; mf < 4; mf++) {
            int mloc0 = m0 + warp_m * 64 + mf * 16 + erow;
            int mloc1 = mloc0 + 8;
            int   t0 = 0, t1 = 0; float w0 = 0.f, w1 = 0.f;
            if (mloc0 < cnt) { t0 = g_pair_token[seg0 + mloc0]; w0 = g_pair_w[seg0 + mloc0]; }
            if (mloc1 < cnt) { t1 = g_pair_token[seg0 + mloc1]; w1 = g_pair_w[seg0 + mloc1]; }
#pragma unroll
            for (int j = 0; j < 4; j++) {
                int nglob = n0 + warp_n * 32 + j * 8 + ecol;
                if (mloc0 < cnt) {
                    atomicAdd(C + (size_t)t0 * HDIM + nglob,     w0 * acc[mf][j][0]);
                    atomicAdd(C + (size_t)t0 * HDIM + nglob + 1, w0 * acc[mf][j][1]);
                }
                if (mloc1 < cnt) {
                    atomicAdd(C + (size_t)t1 * HDIM + nglob,     w1 * acc[mf][j][2]);
                    atomicAdd(C + (size_t)t1 * HDIM + nglob + 1, w1 * acc[mf][j][3]);
                }
            }
        }
    }
}

// ---------------- SwiGLU elementwise: fp32 gu -> pre-split f16 h ----------------
__global__ __launch_bounds__(256) void swiglu_kernel(int npairs)
{
    int idx = blockIdx.x * blockDim.x + threadIdx.x;
    if (idx >= npairs * (IDIM / 4)) return;
    int p = idx / (IDIM / 4);
    int c = idx % (IDIM / 4);
    float4 g4 = ((const float4*)g_gu)[(size_t)p * (TWO_I / 4) + c];
    float4 u4 = ((const float4*)g_gu)[(size_t)p * (TWO_I / 4) + (IDIM / 4) + c];
    float4 h;
    h.x = u4.x * g4.x / (1.f + expf(-g4.x));
    h.y = u4.y * g4.y / (1.f + expf(-g4.y));
    h.z = u4.z * g4.z / (1.f + expf(-g4.z));
    h.w = u4.w * g4.w / (1.f + expf(-g4.w));
    uint32_t h01, h23, l01, l23;
    split4h(h, h01, h23, l01, l23);
    ((uint2*)g_h_hi)[idx] = make_uint2(h01, h23);
    ((uint2*)g_h_lo)[idx] = make_uint2(l01, l23);
}

// ---------------- launch ----------------
extern "C" void kernel_launch(void* const* d_in, const int* in_sizes, int n_in,
                              void* d_out, int out_size)
{
    const float* x   = (const float*)d_in[0];
    const float* gw  = (const float*)d_in[1];
    const float* gup = (const float*)d_in[2];
    const float* dw  = (const float*)d_in[3];
    float* out = (float*)d_out;

    int T = in_sizes[0] / HDIM;
    size_t main_sz = (size_t)T * HDIM;

    float* logits;
    if ((size_t)out_size >= main_sz + (size_t)T * NEXP) logits = out + main_sz;
    else cudaGetSymbolAddress((void**)&logits, g_logits_fallback);

    cudaFuncSetAttribute((const void*)gemm2<HDIM, 0>,
                         cudaFuncAttributeMaxDynamicSharedMemorySize, GSMEM);
    cudaFuncSetAttribute((const void*)gemm2<IDIM, 1>,
                         cudaFuncAttributeMaxDynamicSharedMemorySize, GSMEM);

    int* d_count; cudaGetSymbolAddress((void**)&d_count, g_count);
    cudaMemsetAsync(d_count, 0, NEXP * sizeof(int), 0);
    cudaMemsetAsync(out, 0, main_sz * sizeof(float), 0);   // down scatters into out

    router_kernel<<<T, 128>>>(x, gw, logits, T);
    dispatch_kernel<<<1, 1024>>>(T);

    int mtiles = (T + 127) / 128;
    float* d_gu; cudaGetSymbolAddress((void**)&d_gu, g_gu);

    dim3 gu_grid(mtiles, TWO_I / 128, NEXP);
    gemm2<HDIM, 0><<<gu_grid, 256, GSMEM>>>(x, gup, d_gu, TWO_I, (size_t)TWO_I * HDIM);

    int npairs = 2 * T;
    swiglu_kernel<<<(npairs * (IDIM / 4) + 255) / 256, 256>>>(npairs);

    dim3 dn_grid(mtiles, HDIM / 128, NEXP);
    gemm2<IDIM, 1><<<dn_grid, 256, GSMEM>>>(nullptr, dw, out, HDIM, (size_t)HDIM * IDIM);
}

// round 13
// speedup vs baseline: 3.1925x; 1.0800x over previous
#include <cuda_runtime.h>
#include <cuda_fp16.h>
#include <math.h>
#include <stdint.h>

#define HDIM 2048
#define NEXP 16
#define IDIM 768
#define TWO_I 1536
#define TMAX 2048
#define PMAX (TMAX*2)

typedef unsigned short ushort_t;

// ---------------- device scratch ----------------
__device__ int   g_count[NEXP];
__device__ int   g_segstart[NEXP + 1];
__device__ int   g_tok_e[TMAX * 2];
__device__ float g_tok_w[TMAX * 2];
__device__ int   g_pair_token[PMAX];
__device__ float g_pair_w[PMAX];
__device__ __align__(16) ushort_t g_x_hi[(size_t)TMAX * HDIM];   // x digit1 (f16)
__device__ __align__(16) ushort_t g_x_lo[(size_t)TMAX * HDIM];   // x digit2 (f16)
__device__ __align__(16) float    g_gu[(size_t)PMAX * TWO_I];
__device__ __align__(16) ushort_t g_h_hi[(size_t)PMAX * IDIM];   // h digit1 (f16)
__device__ __align__(16) ushort_t g_h_lo[(size_t)PMAX * IDIM];   // h digit2 (f16)
__device__ float g_logits_fallback[TMAX * NEXP];

// ---------------- portable PTX helpers ----------------
__device__ __forceinline__ uint32_t smem_u32(const void* p) {
    uint32_t a;
    asm("{ .reg .u64 t; cvta.to.shared.u64 t, %1; cvt.u32.u64 %0, t; }" : "=r"(a) : "l"(p));
    return a;
}
#define LDMX4(r, addr) \
    asm volatile("ldmatrix.sync.aligned.m8n8.x4.shared.b16 {%0,%1,%2,%3}, [%4];" \
        : "=r"((r)[0]), "=r"((r)[1]), "=r"((r)[2]), "=r"((r)[3]) : "r"(addr))
#define MMA(acc, a, b0, b1) \
    asm volatile("mma.sync.aligned.m16n8k16.row.col.f32.f16.f16.f32 " \
        "{%0,%1,%2,%3}, {%4,%5,%6,%7}, {%8,%9}, {%0,%1,%2,%3};" \
        : "+f"((acc)[0]), "+f"((acc)[1]), "+f"((acc)[2]), "+f"((acc)[3]) \
        : "r"((a)[0]), "r"((a)[1]), "r"((a)[2]), "r"((a)[3]), "r"(b0), "r"(b1))
#define STSV2(addr, x, y) \
    asm volatile("st.shared.v2.b32 [%0], {%1,%2};" :: "r"((uint32_t)(addr)), "r"(x), "r"(y) : "memory")
#define STSV4(addr, x, y, z, w) \
    asm volatile("st.shared.v4.b32 [%0], {%1,%2,%3,%4};" :: "r"((uint32_t)(addr)), \
        "r"(x), "r"(y), "r"(z), "r"(w) : "memory")

// XOR swizzle for 64B-pitch rows (16B-granular; never add offsets after swizzling)
__device__ __forceinline__ uint32_t swz(uint32_t row, uint32_t colbyte) {
    return (row * 64 + colbyte) ^ ((row & 6) << 3);
}

// f16 pack: {x,y} -> f16x2 (x low)
__device__ __forceinline__ uint32_t packh2(float x, float y) {
    uint32_t r;
    asm("cvt.rn.f16x2.f32 %0, %1, %2;" : "=r"(r) : "f"(y), "f"(x));
    return r;
}
// f16 two-digit split
__device__ __forceinline__ void split2h(float x, float y, uint32_t& hi, uint32_t& lo) {
    uint32_t h = packh2(x, y);
    float hx, hy;
    asm("{ .reg .f16 a,b; mov.b32 {a,b}, %2; cvt.f32.f16 %0, a; cvt.f32.f16 %1, b; }"
        : "=f"(hx), "=f"(hy) : "r"(h));
    lo = packh2(x - hx, y - hy);
    hi = h;
}
__device__ __forceinline__ void split4h(float4 v, uint32_t& h01, uint32_t& h23,
                                        uint32_t& l01, uint32_t& l23) {
    split2h(v.x, v.y, h01, l01);
    split2h(v.z, v.w, h23, l23);
}

// ---------------- router + x pre-split ----------------
__global__ __launch_bounds__(128) void router_kernel(
    const float* __restrict__ x, const float* __restrict__ gw, float* __restrict__ logits, int T)
{
    int t = blockIdx.x, tid = threadIdx.x;
    float acc[NEXP];
#pragma unroll
    for (int e = 0; e < NEXP; e++) acc[e] = 0.f;
    const float* xr = x + (size_t)t * HDIM;
    for (int h = tid; h < HDIM; h += 128) {
        float xv = xr[h];
#pragma unroll
        for (int e = 0; e < NEXP; e++) acc[e] += xv * gw[e * HDIM + h];
    }
#pragma unroll
    for (int e = 0; e < NEXP; e++)
#pragma unroll
        for (int off = 16; off > 0; off >>= 1) acc[e] += __shfl_down_sync(0xffffffffu, acc[e], off);
    __shared__ float sred[4][NEXP];
    __shared__ float slog[NEXP];
    int warp = tid >> 5, lane = tid & 31;
    if (lane == 0)
#pragma unroll
        for (int e = 0; e < NEXP; e++) sred[warp][e] = acc[e];
    __syncthreads();
    if (tid < NEXP) {
        float v = sred[0][tid] + sred[1][tid] + sred[2][tid] + sred[3][tid];
        slog[tid] = v;
        logits[t * NEXP + tid] = v;
    }
    __syncthreads();

    // pre-split x row into f16 hi/lo planes (vectorized, coalesced)
    for (int c = tid * 4; c < HDIM; c += 128 * 4) {
        float4 v = *(const float4*)(xr + c);
        uint32_t h01, h23, l01, l23;
        split4h(v, h01, h23, l01, l23);
        *(uint2*)(g_x_hi + (size_t)t * HDIM + c) = make_uint2(h01, h23);
        *(uint2*)(g_x_lo + (size_t)t * HDIM + c) = make_uint2(l01, l23);
    }

    if (tid == 0) {
        int i0 = 0; float v0 = slog[0];
#pragma unroll
        for (int e = 1; e < NEXP; e++) if (slog[e] > v0) { v0 = slog[e]; i0 = e; }
        int i1 = -1; float v1 = -INFINITY;
#pragma unroll
        for (int e = 0; e < NEXP; e++) { if (e == i0) continue; if (slog[e] > v1) { v1 = slog[e]; i1 = e; } }
        float e1 = expf(v1 - v0);
        float inv = 1.f / (1.f + e1);
        g_tok_e[t * 2 + 0] = i0; g_tok_w[t * 2 + 0] = inv;
        g_tok_e[t * 2 + 1] = i1; g_tok_w[t * 2 + 1] = e1 * inv;
        atomicAdd(&g_count[i0], 1);
        atomicAdd(&g_count[i1], 1);
    }
}

// offsets + dispatch merged, single block
__global__ __launch_bounds__(1024) void dispatch_kernel(int T)
{
    __shared__ int cur[NEXP];
    int tid = threadIdx.x;
    if (tid == 0) {
        int off = 0;
#pragma unroll
        for (int e = 0; e < NEXP; e++) { g_segstart[e] = off; cur[e] = off; off += g_count[e]; }
        g_segstart[NEXP] = off;
    }
    __syncthreads();
    for (int t = tid; t < T; t += 1024) {
#pragma unroll
        for (int s = 0; s < 2; s++) {
            int e = g_tok_e[t * 2 + s];
            int pos = atomicAdd(&cur[e], 1);
            g_pair_token[pos] = t;
            g_pair_w[pos]     = g_tok_w[t * 2 + s];
        }
    }
}

// ---------------- grouped GEMM: pre-split f16 A (2 planes) x single-f16 B ----------------
// CTA 128x128, 256 threads, 8 warps (4m x 2n), warp tile 32x64, BK=32.
// Stage: A_hi 0 (8K) | A_lo 8K (8K) | B 16K (8K) = 24KB; 2 stages = 48KB.
#define STAGE 24576
#define GSMEM 49152

// GATHER 1: A row = g_pair_token (gu, C = g_gu); GATHER 0: A row = pair index (down, atomic scatter)
template<int KDIM, bool GATHER>
__global__ __launch_bounds__(256, 1) void gemm2(
    const ushort_t* __restrict__ Ahi, const ushort_t* __restrict__ Alo,
    const float* __restrict__ B,
    float* __restrict__ C, int ldc, size_t b_expert_stride)
{
    int e = blockIdx.z;
    int seg0 = g_segstart[e];
    int cnt  = g_segstart[e + 1] - seg0;
    int m0 = blockIdx.x * 128;
    if (m0 >= cnt) return;
    int n0 = blockIdx.y * 128;

    extern __shared__ char smem[];
    uint32_t sbase = smem_u32(smem);

    int tid = threadIdx.x;
    int lane = tid & 31, wid = tid >> 5;
    int warp_m = wid >> 1;     // 0..3
    int warp_n = wid & 1;      // 0..1

    // -------- loader setup --------
    int row  = tid >> 1;          // 0..127
    int half = tid & 1;
    int mrow = m0 + row; if (mrow >= cnt) mrow = cnt - 1;
    int arow = GATHER ? g_pair_token[seg0 + mrow] : (seg0 + mrow);
    const uint4* ahip = (const uint4*)(Ahi + (size_t)arow * KDIM) + half * 2;
    const uint4* alop = (const uint4*)(Alo + (size_t)arow * KDIM) + half * 2;
    const float* bptr = B + (size_t)e * b_expert_stride + (size_t)(n0 + row) * KDIM + half * 16;

    uint32_t sts8[4], sts16[2];
#pragma unroll
    for (int j = 0; j < 4; j++) sts8[j] = swz((uint32_t)row, (uint32_t)(half * 32 + j * 8));
#pragma unroll
    for (int j = 0; j < 2; j++) sts16[j] = swz((uint32_t)row, (uint32_t)(half * 32 + j * 16));

    // -------- ldmatrix offsets --------
    int a_r = lane & 15, a_k = lane >> 4;
    int b_n = (lane & 7) + ((lane & 16) ? 8 : 0);
    int b_k = (lane & 8) ? 1 : 0;
    uint32_t a_off[2][2], b_off[4][2];
#pragma unroll
    for (int mf = 0; mf < 2; mf++)
#pragma unroll
        for (int kk = 0; kk < 2; kk++)
            a_off[mf][kk] = swz((uint32_t)(warp_m * 32 + mf * 16 + a_r), (uint32_t)((kk * 2 + a_k) * 16));
#pragma unroll
    for (int nf = 0; nf < 4; nf++)
#pragma unroll
        for (int kk = 0; kk < 2; kk++)
            b_off[nf][kk] = 16384 + swz((uint32_t)(warp_n * 64 + nf * 16 + b_n), (uint32_t)((kk * 2 + b_k) * 16));

    float acc[2][8][4];
#pragma unroll
    for (int mf = 0; mf < 2; mf++)
#pragma unroll
        for (int j = 0; j < 8; j++)
#pragma unroll
            for (int q = 0; q < 4; q++) acc[mf][j][q] = 0.f;

    const int NCH = KDIM / 32;
    float4 pb[4];
    uint4  pah[2], pal[2];

    auto ldg_chunk = [&](int c) {
        const float* bp = bptr + c * 32;
#pragma unroll
        for (int j = 0; j < 4; j++) pb[j] = ((const float4*)bp)[j];
#pragma unroll
        for (int j = 0; j < 2; j++) { pah[j] = ahip[c * 4 + j]; pal[j] = alop[c * 4 + j]; }
    };
    auto sts_chunk = [&](uint32_t sb) {
#pragma unroll
        for (int j = 0; j < 2; j++) {
            STSV4(sb + sts16[j],        pah[j].x, pah[j].y, pah[j].z, pah[j].w);
            STSV4(sb + 8192 + sts16[j], pal[j].x, pal[j].y, pal[j].z, pal[j].w);
        }
#pragma unroll
        for (int j = 0; j < 4; j++) {
            uint32_t b01 = packh2(pb[j].x, pb[j].y);
            uint32_t b23 = packh2(pb[j].z, pb[j].w);
            STSV2(sb + 16384 + sts8[j], b01, b23);
        }
    };

    ldg_chunk(0);
    sts_chunk(sbase);
    ldg_chunk(1);
    __syncthreads();

#pragma unroll 2
    for (int ch = 0; ch < NCH; ch++) {
        uint32_t sb  = sbase + (ch & 1) * STAGE;
        uint32_t sbn = sbase + ((ch + 1) & 1) * STAGE;
        if (ch + 1 < NCH) sts_chunk(sbn);
#pragma unroll
        for (int kk = 0; kk < 2; kk++) {
            uint32_t ahf[2][4], alf[2][4];
#pragma unroll
            for (int mf = 0; mf < 2; mf++) {
                LDMX4(ahf[mf], sb + a_off[mf][kk]);
                LDMX4(alf[mf], sb + 8192 + a_off[mf][kk]);
            }
#pragma unroll
            for (int nf = 0; nf < 4; nf++) {
                uint32_t bf[4];
                LDMX4(bf, sb + b_off[nf][kk]);
#pragma unroll
                for (int mf = 0; mf < 2; mf++)
#pragma unroll
                    for (int jj = 0; jj < 2; jj++) {
                        int j = nf * 2 + jj;
                        MMA(acc[mf][j], ahf[mf], bf[jj * 2], bf[jj * 2 + 1]);
                        MMA(acc[mf][j], alf[mf], bf[jj * 2], bf[jj * 2 + 1]);
                    }
            }
        }
        if (ch + 2 < NCH) ldg_chunk(ch + 2);
        __syncthreads();
    }

    // -------- epilogue --------
    int erow = lane >> 2;
    int ecol = (lane & 3) * 2;
    if (GATHER) {
        // gu: direct store to g_gu
#pragma unroll
        for (int mf = 0; mf < 2; mf++) {
            int mloc0 = m0 + warp_m * 32 + mf * 16 + erow;
            int mloc1 = mloc0 + 8;
#pragma unroll
            for (int j = 0; j < 8; j++) {
                int nglob = n0 + warp_n * 64 + j * 8 + ecol;
                if (mloc0 < cnt)
                    *(float2*)(C + (size_t)(seg0 + mloc0) * ldc + nglob) = make_float2(acc[mf][j][0], acc[mf][j][1]);
                if (mloc1 < cnt)
                    *(float2*)(C + (size_t)(seg0 + mloc1) * ldc + nglob) = make_float2(acc[mf][j][2], acc[mf][j][3]);
            }
        }
    } else {
        // down: weighted atomic scatter into out[t, n]
#pragma unroll
        for (int mf = 0; mf < 2; mf++) {
            int mloc0 = m0 + warp_m * 32 + mf * 16 + erow;
            int mloc1 = mloc0 + 8;
            int   t0 = 0, t1 = 0; float w0 = 0.f, w1 = 0.f;
            if (mloc0 < cnt) { t0 = g_pair_token[seg0 + mloc0]; w0 = g_pair_w[seg0 + mloc0]; }
            if (mloc1 < cnt) { t1 = g_pair_token[seg0 + mloc1]; w1 = g_pair_w[seg0 + mloc1]; }
#pragma unroll
            for (int j = 0; j < 8; j++) {
                int nglob = n0 + warp_n * 64 + j * 8 + ecol;
                if (mloc0 < cnt) {
                    atomicAdd(C + (size_t)t0 * HDIM + nglob,     w0 * acc[mf][j][0]);
                    atomicAdd(C + (size_t)t0 * HDIM + nglob + 1, w0 * acc[mf][j][1]);
                }
                if (mloc1 < cnt) {
                    atomicAdd(C + (size_t)t1 * HDIM + nglob,     w1 * acc[mf][j][2]);
                    atomicAdd(C + (size_t)t1 * HDIM + nglob + 1, w1 * acc[mf][j][3]);
                }
            }
        }
    }
}

// ---------------- SwiGLU elementwise: fp32 gu -> pre-split f16 h ----------------
__global__ __launch_bounds__(256) void swiglu_kernel(int npairs)
{
    int idx = blockIdx.x * blockDim.x + threadIdx.x;
    if (idx >= npairs * (IDIM / 4)) return;
    int p = idx / (IDIM / 4);
    int c = idx % (IDIM / 4);
    float4 g4 = ((const float4*)g_gu)[(size_t)p * (TWO_I / 4) + c];
    float4 u4 = ((const float4*)g_gu)[(size_t)p * (TWO_I / 4) + (IDIM / 4) + c];
    float4 h;
    h.x = u4.x * g4.x / (1.f + expf(-g4.x));
    h.y = u4.y * g4.y / (1.f + expf(-g4.y));
    h.z = u4.z * g4.z / (1.f + expf(-g4.z));
    h.w = u4.w * g4.w / (1.f + expf(-g4.w));
    uint32_t h01, h23, l01, l23;
    split4h(h, h01, h23, l01, l23);
    ((uint2*)g_h_hi)[idx] = make_uint2(h01, h23);
    ((uint2*)g_h_lo)[idx] = make_uint2(l01, l23);
}

// ---------------- launch ----------------
extern "C" void kernel_launch(void* const* d_in, const int* in_sizes, int n_in,
                              void* d_out, int out_size)
{
    const float* x   = (const float*)d_in[0];
    const float* gw  = (const float*)d_in[1];
    const float* gup = (const float*)d_in[2];
    const float* dw  = (const float*)d_in[3];
    float* out = (float*)d_out;

    int T = in_sizes[0] / HDIM;
    size_t main_sz = (size_t)T * HDIM;

    float* logits;
    if ((size_t)out_size >= main_sz + (size_t)T * NEXP) logits = out + main_sz;
    else cudaGetSymbolAddress((void**)&logits, g_logits_fallback);

    cudaFuncSetAttribute((const void*)gemm2<HDIM, true>,
                         cudaFuncAttributeMaxDynamicSharedMemorySize, GSMEM);
    cudaFuncSetAttribute((const void*)gemm2<IDIM, false>,
                         cudaFuncAttributeMaxDynamicSharedMemorySize, GSMEM);

    int* d_count; cudaGetSymbolAddress((void**)&d_count, g_count);
    cudaMemsetAsync(d_count, 0, NEXP * sizeof(int), 0);
    cudaMemsetAsync(out, 0, main_sz * sizeof(float), 0);   // down scatters into out

    router_kernel<<<T, 128>>>(x, gw, logits, T);
    dispatch_kernel<<<1, 1024>>>(T);

    int mtiles = (T + 127) / 128;
    float* d_gu; cudaGetSymbolAddress((void**)&d_gu, g_gu);
    ushort_t *d_xh, *d_xl, *d_hh, *d_hl;
    cudaGetSymbolAddress((void**)&d_xh, g_x_hi);
    cudaGetSymbolAddress((void**)&d_xl, g_x_lo);
    cudaGetSymbolAddress((void**)&d_hh, g_h_hi);
    cudaGetSymbolAddress((void**)&d_hl, g_h_lo);

    dim3 gu_grid(mtiles, TWO_I / 128, NEXP);
    gemm2<HDIM, true><<<gu_grid, 256, GSMEM>>>(d_xh, d_xl, gup, d_gu, TWO_I, (size_t)TWO_I * HDIM);

    int npairs = 2 * T;
    swiglu_kernel<<<(npairs * (IDIM / 4) + 255) / 256, 256>>>(npairs);

    dim3 dn_grid(mtiles, HDIM / 128, NEXP);
    gemm2<IDIM, false><<<dn_grid, 256, GSMEM>>>(d_hh, d_hl, dw, out, HDIM, (size_t)HDIM * IDIM);
}